// round 6
// baseline (speedup 1.0000x reference)
#include <cuda_runtime.h>
#include <cuda_fp16.h>
#include <math.h>

#define NN      50000   // nodes
#define FF      128     // features
#define EE      600000  // edges (before self loops)
#define EP      (EE + NN)
#define NID     5000
// dh = 16, scale = 0.25

// ---------------- device scratch (static; no allocations) ----------------
__device__ __half g_Qh[NN * FF];
__device__ __half g_Kh[NN * FF];
__device__ __half g_Vh[NN * FF];
__device__ int    g_deg[NN];      // zero-initialized at load; scan re-zeros it
__device__ int    g_offs[NN + 1];
__device__ int    g_cursor[NN];
__device__ int    g_scol[EP];

// ---------------- helpers ----------------
__device__ __forceinline__ unsigned f2tf(float f) {
    unsigned r;
    asm("cvt.rna.tf32.f32 %0, %1;" : "=r"(r) : "f"(f));
    return r;
}

__device__ __forceinline__ void mma_tf32(float* c, const unsigned* a, const unsigned* b) {
    asm volatile(
        "mma.sync.aligned.m16n8k8.row.col.f32.tf32.tf32.f32 "
        "{%0,%1,%2,%3},{%4,%5,%6,%7},{%8,%9},{%0,%1,%2,%3};"
        : "+f"(c[0]), "+f"(c[1]), "+f"(c[2]), "+f"(c[3])
        : "r"(a[0]), "r"(a[1]), "r"(a[2]), "r"(a[3]), "r"(b[0]), "r"(b[1]));
}

__device__ __forceinline__ void cp_async16(void* dst_smem, const void* src) {
    unsigned d = (unsigned)__cvta_generic_to_shared(dst_smem);
    asm volatile("cp.async.cg.shared.global [%0], [%1], 16;" :: "r"(d), "l"(src));
}
__device__ __forceinline__ void cp_commit() {
    asm volatile("cp.async.commit_group;");
}
template <int N>
__device__ __forceinline__ void cp_wait() {
    asm volatile("cp.async.wait_group %0;" :: "n"(N));
}

// ---------------- tf32 QKV GEMM with cp.async double buffering -------------
// blockIdx.y: 0->Q(relu+bias), 1->K(relu+bias), 2->V(plain)
#define AS_STRIDE 20
#define BS_STRIDE 136

__global__ __launch_bounds__(256, 2) void gemm3_kernel(
    const float* __restrict__ x,
    const float* __restrict__ Wq, const float* __restrict__ bq,
    const float* __restrict__ Wk, const float* __restrict__ bk,
    const float* __restrict__ Wv)
{
    const int which = blockIdx.y;
    const float* W    = (which == 0) ? Wq : (which == 1) ? Wk : Wv;
    const float* bias = (which == 0) ? bq : (which == 1) ? bk : nullptr;
    __half* out = (which == 0) ? g_Qh : (which == 1) ? g_Kh : g_Vh;

    __shared__ float As[2][128 * AS_STRIDE];
    __shared__ float Bs[2][16 * BS_STRIDE];

    const int tid  = threadIdx.x;
    const int lane = tid & 31;
    const int warp = tid >> 5;
    const int wm   = warp >> 1;
    const int wn   = warp & 1;
    const int rowBase = blockIdx.x * 128;

    const int aG0 = tid * 2, aG1 = tid * 2 + 1;
    const int aR0 = aG0 >> 2, aC0 = (aG0 & 3) * 4;
    const int aR1 = aG1 >> 2, aC1 = (aG1 & 3) * 4;
    const int gRow0 = min(rowBase + aR0, NN - 1);
    const int gRow1 = min(rowBase + aR1, NN - 1);
    const int bR0 = aG0 >> 5, bC0 = (aG0 & 31) * 4;
    const int bR1 = aG1 >> 5, bC1 = (aG1 & 31) * 4;

    auto prefetch = [&](int kc, int buf) {
        cp_async16(&As[buf][aR0 * AS_STRIDE + aC0], &x[(size_t)gRow0 * FF + kc + aC0]);
        cp_async16(&As[buf][aR1 * AS_STRIDE + aC1], &x[(size_t)gRow1 * FF + kc + aC1]);
        cp_async16(&Bs[buf][bR0 * BS_STRIDE + bC0], &W[(size_t)(kc + bR0) * FF + bC0]);
        cp_async16(&Bs[buf][bR1 * BS_STRIDE + bC1], &W[(size_t)(kc + bR1) * FF + bC1]);
        cp_commit();
    };

    float acc[2][8][4];
#pragma unroll
    for (int i = 0; i < 2; i++)
#pragma unroll
        for (int j = 0; j < 8; j++)
#pragma unroll
            for (int t = 0; t < 4; t++) acc[i][j][t] = 0.f;

    const int lq = lane >> 2;
    const int lr = lane & 3;

    prefetch(0, 0);

    for (int c = 0; c < 8; c++) {
        const int buf = c & 1;
        if (c + 1 < 8) prefetch((c + 1) * 16, (c + 1) & 1);
        if (c + 1 < 8) cp_wait<1>(); else cp_wait<0>();
        __syncthreads();

        const float* Ab = As[buf];
        const float* Bb = Bs[buf];
#pragma unroll
        for (int kk = 0; kk < 2; kk++) {
            unsigned bf[8][2];
#pragma unroll
            for (int j = 0; j < 8; j++) {
                int n = wn * 64 + j * 8 + lq;
                bf[j][0] = f2tf(Bb[(kk * 8 + lr) * BS_STRIDE + n]);
                bf[j][1] = f2tf(Bb[(kk * 8 + lr + 4) * BS_STRIDE + n]);
            }
            unsigned af[2][4];
#pragma unroll
            for (int i = 0; i < 2; i++) {
                int r0 = wm * 32 + i * 16 + lq;
                af[i][0] = f2tf(Ab[r0 * AS_STRIDE + kk * 8 + lr]);
                af[i][1] = f2tf(Ab[(r0 + 8) * AS_STRIDE + kk * 8 + lr]);
                af[i][2] = f2tf(Ab[r0 * AS_STRIDE + kk * 8 + lr + 4]);
                af[i][3] = f2tf(Ab[(r0 + 8) * AS_STRIDE + kk * 8 + lr + 4]);
            }
#pragma unroll
            for (int i = 0; i < 2; i++)
#pragma unroll
                for (int j = 0; j < 8; j++)
                    mma_tf32(acc[i][j], af[i], bf[j]);
        }
        __syncthreads();
    }

    // ---- epilogue: bias (+relu) -> half2 store ----
#pragma unroll
    for (int i = 0; i < 2; i++) {
#pragma unroll
        for (int j = 0; j < 8; j++) {
            int col = wn * 64 + j * 8 + lr * 2;
            float b0 = 0.f, b1 = 0.f;
            if (which < 2) { b0 = bias[col]; b1 = bias[col + 1]; }
            int r0 = rowBase + wm * 32 + i * 16 + lq;
            int r1 = r0 + 8;
            float v00 = acc[i][j][0] + b0, v01 = acc[i][j][1] + b1;
            float v10 = acc[i][j][2] + b0, v11 = acc[i][j][3] + b1;
            if (which < 2) {
                v00 = fmaxf(v00, 0.f); v01 = fmaxf(v01, 0.f);
                v10 = fmaxf(v10, 0.f); v11 = fmaxf(v11, 0.f);
            }
            if (r0 < NN)
                *reinterpret_cast<__half2*>(&out[(size_t)r0 * FF + col]) =
                    __floats2half2_rn(v00, v01);
            if (r1 < NN)
                *reinterpret_cast<__half2*>(&out[(size_t)r1 * FF + col]) =
                    __floats2half2_rn(v10, v11);
        }
    }
}

// -------- id scatter GEMM: V[id] += x[id] @ kernel_id --------
#define IDB 16
__global__ __launch_bounds__(256) void idgemm_kernel(
    const float* __restrict__ x,
    const int* __restrict__ id_index,
    const float* __restrict__ Wid)
{
    __shared__ float xs[IDB][FF];
    __shared__ float red[IDB][FF];
    __shared__ int ids[IDB];

    const int tid = threadIdx.x;
    const int base = blockIdx.x * IDB;
    const int nid = min(IDB, NID - base);

    if (tid < nid) ids[tid] = id_index[base + tid];
    __syncthreads();

    for (int i = tid; i < IDB * FF; i += 256) {
        int r = i >> 7;
        if (r < nid) xs[r][i & 127] = x[(size_t)ids[r] * FF + (i & 127)];
    }
    __syncthreads();

    const int col = tid & 127;
    const int half = tid >> 7;
    float acc[IDB];
#pragma unroll
    for (int i = 0; i < IDB; i++) acc[i] = 0.f;

    const int k0 = half * 64;
#pragma unroll 4
    for (int k = k0; k < k0 + 64; k++) {
        const float w = Wid[k * FF + col];
#pragma unroll
        for (int i = 0; i < IDB; i++)
            acc[i] = fmaf(xs[i][k], w, acc[i]);
    }

    if (half == 1) {
#pragma unroll
        for (int i = 0; i < IDB; i++) red[i][col] = acc[i];
    }
    __syncthreads();
    if (half == 0) {
#pragma unroll
        for (int i = 0; i < IDB; i++) {
            float s = acc[i] + red[i][col];
            float s_hi = __shfl_down_sync(0xffffffff, s, 1);
            if (((col & 1) == 0) && i < nid)
                atomicAdd(reinterpret_cast<__half2*>(&g_Vh[(size_t)ids[i] * FF + col]),
                          __floats2half2_rn(s, s_hi));
        }
    }
}

// ---------------- histogram of destination (row) degrees ----------------
__global__ void hist_kernel(const int* __restrict__ ei) {
    int e = blockIdx.x * blockDim.x + threadIdx.x;
    if (e < EP) {
        int row = (e < EE) ? ei[e] : (e - EE);
        atomicAdd(&g_deg[row], 1);
    }
}

// ------- single-block exclusive scan over degrees (re-zeros g_deg) -------
__global__ void scan_kernel() {
    __shared__ int part[1024];
    const int t = threadIdx.x;
    const int CH = (NN + 1023) / 1024;
    const int base = t * CH;
    int s = 0;
    for (int i = 0; i < CH; i++) {
        int idx = base + i;
        if (idx < NN) s += g_deg[idx];
    }
    part[t] = s;
    __syncthreads();
    for (int off = 1; off < 1024; off <<= 1) {
        int v = (t >= off) ? part[t - off] : 0;
        __syncthreads();
        part[t] += v;
        __syncthreads();
    }
    int run = (t == 0) ? 0 : part[t - 1];
    for (int i = 0; i < CH; i++) {
        int idx = base + i;
        if (idx < NN) {
            g_offs[idx] = run;
            g_cursor[idx] = run;
            run += g_deg[idx];
            g_deg[idx] = 0;          // reset for next replay
        }
    }
    if (t == 1023) g_offs[NN] = run;
}

// ---------------- scatter edges into destination-sorted order ----------------
__global__ void scatter_kernel(const int* __restrict__ ei) {
    int e = blockIdx.x * blockDim.x + threadIdx.x;
    if (e < EP) {
        int row, col;
        if (e < EE) { row = ei[e]; col = ei[EE + e]; }
        else        { row = e - EE; col = row; }
        int pos = atomicAdd(&g_cursor[row], 1);
        g_scol[pos] = col;
    }
}

// -------- per-node attention aggregation (one warp per node, fp16 gathers) ---
// 2x unrolled edge loop (empirically fastest; 4x regressed ~50us)
__global__ __launch_bounds__(256) void aggregate_kernel(
    const float* __restrict__ bias, float* __restrict__ out)
{
    const int n = (blockIdx.x * blockDim.x + threadIdx.x) >> 5;
    const int lane = threadIdx.x & 31;
    if (n >= NN) return;

    uint2 qu = *reinterpret_cast<const uint2*>(&g_Qh[(size_t)n * FF + lane * 4]);
    const float2 q0 = __half22float2(*reinterpret_cast<__half2*>(&qu.x));
    const float2 q1 = __half22float2(*reinterpret_cast<__half2*>(&qu.y));

    float a0 = 0.f, a1 = 0.f, a2 = 0.f, a3 = 0.f;
    float denom = 0.f;

    const int s = g_offs[n];
    const int e = g_offs[n + 1];
    int p = s;

    for (; p + 2 <= e; p += 2) {
        const int c0 = g_scol[p];
        const int c1 = g_scol[p + 1];
        uint2 k0 = *reinterpret_cast<const uint2*>(&g_Kh[(size_t)c0 * FF + lane * 4]);
        uint2 k1 = *reinterpret_cast<const uint2*>(&g_Kh[(size_t)c1 * FF + lane * 4]);
        uint2 v0 = *reinterpret_cast<const uint2*>(&g_Vh[(size_t)c0 * FF + lane * 4]);
        uint2 v1 = *reinterpret_cast<const uint2*>(&g_Vh[(size_t)c1 * FF + lane * 4]);

        float2 ka = __half22float2(*reinterpret_cast<__half2*>(&k0.x));
        float2 kb = __half22float2(*reinterpret_cast<__half2*>(&k0.y));
        float d0 = q0.x * ka.x + q0.y * ka.y + q1.x * kb.x + q1.y * kb.y;
        ka = __half22float2(*reinterpret_cast<__half2*>(&k1.x));
        kb = __half22float2(*reinterpret_cast<__half2*>(&k1.y));
        float d1 = q0.x * ka.x + q0.y * ka.y + q1.x * kb.x + q1.y * kb.y;

        d0 += __shfl_xor_sync(0xffffffff, d0, 1);
        d1 += __shfl_xor_sync(0xffffffff, d1, 1);
        d0 += __shfl_xor_sync(0xffffffff, d0, 2);
        d1 += __shfl_xor_sync(0xffffffff, d1, 2);

        const float w0 = __expf(d0 * 0.25f);
        const float w1 = __expf(d1 * 0.25f);

        float2 va = __half22float2(*reinterpret_cast<__half2*>(&v0.x));
        float2 vb = __half22float2(*reinterpret_cast<__half2*>(&v0.y));
        a0 = fmaf(w0, va.x, a0); a1 = fmaf(w0, va.y, a1);
        a2 = fmaf(w0, vb.x, a2); a3 = fmaf(w0, vb.y, a3);
        va = __half22float2(*reinterpret_cast<__half2*>(&v1.x));
        vb = __half22float2(*reinterpret_cast<__half2*>(&v1.y));
        a0 = fmaf(w1, va.x, a0); a1 = fmaf(w1, va.y, a1);
        a2 = fmaf(w1, vb.x, a2); a3 = fmaf(w1, vb.y, a3);
        denom += w0 + w1;
    }
    for (; p < e; p++) {
        const int c0 = g_scol[p];
        uint2 k0 = *reinterpret_cast<const uint2*>(&g_Kh[(size_t)c0 * FF + lane * 4]);
        float2 ka = __half22float2(*reinterpret_cast<__half2*>(&k0.x));
        float2 kb = __half22float2(*reinterpret_cast<__half2*>(&k0.y));
        float d0 = q0.x * ka.x + q0.y * ka.y + q1.x * kb.x + q1.y * kb.y;
        d0 += __shfl_xor_sync(0xffffffff, d0, 1);
        d0 += __shfl_xor_sync(0xffffffff, d0, 2);
        const float w0 = __expf(d0 * 0.25f);
        uint2 v0 = *reinterpret_cast<const uint2*>(&g_Vh[(size_t)c0 * FF + lane * 4]);
        float2 va = __half22float2(*reinterpret_cast<__half2*>(&v0.x));
        float2 vb = __half22float2(*reinterpret_cast<__half2*>(&v0.y));
        a0 = fmaf(w0, va.x, a0); a1 = fmaf(w0, va.y, a1);
        a2 = fmaf(w0, vb.x, a2); a3 = fmaf(w0, vb.y, a3);
        denom += w0;
    }

    const float inv = 1.f / denom;   // >= 1 edge guaranteed (self loop)
    const float4 b = *reinterpret_cast<const float4*>(&bias[lane * 4]);
    float4 o;
    o.x = fmaf(a0, inv, b.x);
    o.y = fmaf(a1, inv, b.y);
    o.z = fmaf(a2, inv, b.z);
    o.w = fmaf(a3, inv, b.w);
    *reinterpret_cast<float4*>(&out[(size_t)n * FF + lane * 4]) = o;
}

// ---------------- launch ----------------
extern "C" void kernel_launch(void* const* d_in, const int* in_sizes, int n_in,
                              void* d_out, int out_size)
{
    const float* x    = (const float*)d_in[0];
    const int*   ei   = (const int*)d_in[1];     // JAX x64 disabled -> int32
    const int*   idix = (const int*)d_in[2];
    const float* Wq   = (const float*)d_in[3];
    const float* bq   = (const float*)d_in[4];
    const float* Wk   = (const float*)d_in[5];
    const float* bk   = (const float*)d_in[6];
    const float* Wv   = (const float*)d_in[7];
    const float* Wid  = (const float*)d_in[8];
    const float* bo   = (const float*)d_in[9];
    float* out = (float*)d_out;

    // sort chain (needs g_deg==0; scan resets it each call)
    hist_kernel<<<(EP + 255) / 256, 256>>>(ei);
    scan_kernel<<<1, 1024>>>();
    scatter_kernel<<<(EP + 255) / 256, 256>>>(ei);

    // Q/K/V GEMMs (tf32 tensor cores, cp.async pipeline, fp16 outputs)
    dim3 ggrid((NN + 127) / 128, 3);
    gemm3_kernel<<<ggrid, 256>>>(x, Wq, bq, Wk, bk, Wv);

    // id scatter-add GEMM into V
    idgemm_kernel<<<(NID + IDB - 1) / IDB, 256>>>(x, idix, Wid);

    // fused attention softmax + aggregation, one warp per node
    aggregate_kernel<<<(NN * 32 + 255) / 256, 256>>>(bo, out);
}

// round 7
// speedup vs baseline: 1.7514x; 1.7514x over previous
#include <cuda_runtime.h>
#include <cuda_fp16.h>
#include <math.h>

#define NN      50000   // nodes
#define FF      128     // features
#define EE      600000  // edges (before self loops)
#define EP      (EE + NN)
#define NID     5000
#define SB      256
#define NSB     ((NN + SB - 1) / SB)   // 196
// dh = 16, scale = 0.25

// ---------------- device scratch (static; no allocations) ----------------
__device__ __half g_Qh[NN * FF];
__device__ __half g_Kh[NN * FF];
__device__ __half g_Vh[NN * FF];
__device__ int    g_deg[NN];      // zero-initialized at load; scan3 re-zeros it
__device__ int    g_offs[NN + 1];
__device__ int    g_cursor[NN];
__device__ int    g_scol[EP];
__device__ int    g_bsum[NSB];
__device__ int    g_boff[NSB];

// ---------------- helpers ----------------
__device__ __forceinline__ unsigned f2tf(float f) {
    unsigned r;
    asm("cvt.rna.tf32.f32 %0, %1;" : "=r"(r) : "f"(f));
    return r;
}

__device__ __forceinline__ void mma_tf32(float* c, const unsigned* a, const unsigned* b) {
    asm volatile(
        "mma.sync.aligned.m16n8k8.row.col.f32.tf32.tf32.f32 "
        "{%0,%1,%2,%3},{%4,%5,%6,%7},{%8,%9},{%0,%1,%2,%3};"
        : "+f"(c[0]), "+f"(c[1]), "+f"(c[2]), "+f"(c[3])
        : "r"(a[0]), "r"(a[1]), "r"(a[2]), "r"(a[3]), "r"(b[0]), "r"(b[1]));
}

__device__ __forceinline__ void cp_async16(void* dst_smem, const void* src) {
    unsigned d = (unsigned)__cvta_generic_to_shared(dst_smem);
    asm volatile("cp.async.cg.shared.global [%0], [%1], 16;" :: "r"(d), "l"(src));
}
__device__ __forceinline__ void cp_commit() {
    asm volatile("cp.async.commit_group;");
}
template <int N>
__device__ __forceinline__ void cp_wait() {
    asm volatile("cp.async.wait_group %0;" :: "n"(N));
}

// ---------------- tf32 QKV GEMM, 3-stage cp.async pipeline -----------------
// blockIdx.y: 0->Q(relu+bias), 1->K(relu+bias), 2->V(plain)
#define AS_STRIDE 20
#define BS_STRIDE 136
#define A_CHUNK   (128 * AS_STRIDE)     // floats per A stage
#define B_CHUNK   (16 * BS_STRIDE)      // floats per B stage
#define GEMM_SMEM (3 * (A_CHUNK + B_CHUNK) * 4)

__global__ __launch_bounds__(256, 2) void gemm3_kernel(
    const float* __restrict__ x,
    const float* __restrict__ Wq, const float* __restrict__ bq,
    const float* __restrict__ Wk, const float* __restrict__ bk,
    const float* __restrict__ Wv)
{
    const int which = blockIdx.y;
    const float* W    = (which == 0) ? Wq : (which == 1) ? Wk : Wv;
    const float* bias = (which == 0) ? bq : (which == 1) ? bk : nullptr;
    __half* out = (which == 0) ? g_Qh : (which == 1) ? g_Kh : g_Vh;

    extern __shared__ float dynsmem[];
    float* AsB = dynsmem;                 // 3 stages of A
    float* BsB = dynsmem + 3 * A_CHUNK;   // 3 stages of B

    const int tid  = threadIdx.x;
    const int lane = tid & 31;
    const int warp = tid >> 5;
    const int wm   = warp >> 1;
    const int wn   = warp & 1;
    const int rowBase = blockIdx.x * 128;

    const int aG0 = tid * 2, aG1 = tid * 2 + 1;
    const int aR0 = aG0 >> 2, aC0 = (aG0 & 3) * 4;
    const int aR1 = aG1 >> 2, aC1 = (aG1 & 3) * 4;
    const int gRow0 = min(rowBase + aR0, NN - 1);
    const int gRow1 = min(rowBase + aR1, NN - 1);
    const int bR0 = aG0 >> 5, bC0 = (aG0 & 31) * 4;
    const int bR1 = aG1 >> 5, bC1 = (aG1 & 31) * 4;

    auto prefetch = [&](int c) {
        const int kc = c * 16;
        float* As = AsB + (c % 3) * A_CHUNK;
        float* Bs = BsB + (c % 3) * B_CHUNK;
        cp_async16(&As[aR0 * AS_STRIDE + aC0], &x[(size_t)gRow0 * FF + kc + aC0]);
        cp_async16(&As[aR1 * AS_STRIDE + aC1], &x[(size_t)gRow1 * FF + kc + aC1]);
        cp_async16(&Bs[bR0 * BS_STRIDE + bC0], &W[(size_t)(kc + bR0) * FF + bC0]);
        cp_async16(&Bs[bR1 * BS_STRIDE + bC1], &W[(size_t)(kc + bR1) * FF + bC1]);
        cp_commit();
    };

    float acc[2][8][4];
#pragma unroll
    for (int i = 0; i < 2; i++)
#pragma unroll
        for (int j = 0; j < 8; j++)
#pragma unroll
            for (int t = 0; t < 4; t++) acc[i][j][t] = 0.f;

    const int lq = lane >> 2;
    const int lr = lane & 3;

    prefetch(0);
    prefetch(1);

    for (int c = 0; c < 8; c++) {
        if (c + 2 < 8) prefetch(c + 2);
        if (c <= 5) cp_wait<2>();
        else if (c == 6) cp_wait<1>();
        else cp_wait<0>();
        __syncthreads();

        const float* Ab = AsB + (c % 3) * A_CHUNK;
        const float* Bb = BsB + (c % 3) * B_CHUNK;
#pragma unroll
        for (int kk = 0; kk < 2; kk++) {
            unsigned bf[8][2];
#pragma unroll
            for (int j = 0; j < 8; j++) {
                int n = wn * 64 + j * 8 + lq;
                bf[j][0] = f2tf(Bb[(kk * 8 + lr) * BS_STRIDE + n]);
                bf[j][1] = f2tf(Bb[(kk * 8 + lr + 4) * BS_STRIDE + n]);
            }
            unsigned af[2][4];
#pragma unroll
            for (int i = 0; i < 2; i++) {
                int r0 = wm * 32 + i * 16 + lq;
                af[i][0] = f2tf(Ab[r0 * AS_STRIDE + kk * 8 + lr]);
                af[i][1] = f2tf(Ab[(r0 + 8) * AS_STRIDE + kk * 8 + lr]);
                af[i][2] = f2tf(Ab[r0 * AS_STRIDE + kk * 8 + lr + 4]);
                af[i][3] = f2tf(Ab[(r0 + 8) * AS_STRIDE + kk * 8 + lr + 4]);
            }
#pragma unroll
            for (int i = 0; i < 2; i++)
#pragma unroll
                for (int j = 0; j < 8; j++)
                    mma_tf32(acc[i][j], af[i], bf[j]);
        }
        __syncthreads();
    }

    // ---- epilogue: bias (+relu) -> half2 store ----
#pragma unroll
    for (int i = 0; i < 2; i++) {
#pragma unroll
        for (int j = 0; j < 8; j++) {
            int col = wn * 64 + j * 8 + lr * 2;
            float b0 = 0.f, b1 = 0.f;
            if (which < 2) { b0 = bias[col]; b1 = bias[col + 1]; }
            int r0 = rowBase + wm * 32 + i * 16 + lq;
            int r1 = r0 + 8;
            float v00 = acc[i][j][0] + b0, v01 = acc[i][j][1] + b1;
            float v10 = acc[i][j][2] + b0, v11 = acc[i][j][3] + b1;
            if (which < 2) {
                v00 = fmaxf(v00, 0.f); v01 = fmaxf(v01, 0.f);
                v10 = fmaxf(v10, 0.f); v11 = fmaxf(v11, 0.f);
            }
            if (r0 < NN)
                *reinterpret_cast<__half2*>(&out[(size_t)r0 * FF + col]) =
                    __floats2half2_rn(v00, v01);
            if (r1 < NN)
                *reinterpret_cast<__half2*>(&out[(size_t)r1 * FF + col]) =
                    __floats2half2_rn(v10, v11);
        }
    }
}

// -------- id scatter GEMM: V[id] += x[id] @ kernel_id --------
#define IDB 16
__global__ __launch_bounds__(256) void idgemm_kernel(
    const float* __restrict__ x,
    const int* __restrict__ id_index,
    const float* __restrict__ Wid)
{
    __shared__ float xs[IDB][FF];
    __shared__ float red[IDB][FF];
    __shared__ int ids[IDB];

    const int tid = threadIdx.x;
    const int base = blockIdx.x * IDB;
    const int nid = min(IDB, NID - base);

    if (tid < nid) ids[tid] = id_index[base + tid];
    __syncthreads();

    for (int i = tid; i < IDB * FF; i += 256) {
        int r = i >> 7;
        if (r < nid) xs[r][i & 127] = x[(size_t)ids[r] * FF + (i & 127)];
    }
    __syncthreads();

    const int col = tid & 127;
    const int half = tid >> 7;
    float acc[IDB];
#pragma unroll
    for (int i = 0; i < IDB; i++) acc[i] = 0.f;

    const int k0 = half * 64;
#pragma unroll 4
    for (int k = k0; k < k0 + 64; k++) {
        const float w = Wid[k * FF + col];
#pragma unroll
        for (int i = 0; i < IDB; i++)
            acc[i] = fmaf(xs[i][k], w, acc[i]);
    }

    if (half == 1) {
#pragma unroll
        for (int i = 0; i < IDB; i++) red[i][col] = acc[i];
    }
    __syncthreads();
    if (half == 0) {
#pragma unroll
        for (int i = 0; i < IDB; i++) {
            float s = acc[i] + red[i][col];
            float s_hi = __shfl_down_sync(0xffffffff, s, 1);
            if (((col & 1) == 0) && i < nid)
                atomicAdd(reinterpret_cast<__half2*>(&g_Vh[(size_t)ids[i] * FF + col]),
                          __floats2half2_rn(s, s_hi));
        }
    }
}

// ---------------- histogram of destination (row) degrees ----------------
__global__ void hist_kernel(const int* __restrict__ ei) {
    int e = blockIdx.x * blockDim.x + threadIdx.x;
    if (e < EP) {
        int row = (e < EE) ? ei[e] : (e - EE);
        atomicAdd(&g_deg[row], 1);
    }
}

// ---------------- blocked scan: coalesced, 3 tiny kernels -----------------
__global__ void scan1_kernel() {           // per-block degree sums
    const int b = blockIdx.x;
    const int t = threadIdx.x;
    const int i = b * SB + t;
    int v = (i < NN) ? g_deg[i] : 0;
    __shared__ int ws[8];
#pragma unroll
    for (int o = 16; o > 0; o >>= 1) v += __shfl_down_sync(0xffffffff, v, o);
    if ((t & 31) == 0) ws[t >> 5] = v;
    __syncthreads();
    if (t < 8) {
        int s = ws[t];
#pragma unroll
        for (int o = 4; o > 0; o >>= 1) s += __shfl_down_sync(0xff, s, o);
        if (t == 0) g_bsum[b] = s;
    }
}

__global__ void scan2_kernel() {           // scan 196 block sums
    __shared__ int sh[256];
    const int t = threadIdx.x;
    int v = (t < NSB) ? g_bsum[t] : 0;
    sh[t] = v;
    __syncthreads();
    for (int o = 1; o < 256; o <<= 1) {
        int u = (t >= o) ? sh[t - o] : 0;
        __syncthreads();
        sh[t] += u;
        __syncthreads();
    }
    if (t < NSB) g_boff[t] = sh[t] - v;    // exclusive
    if (t == 0) g_offs[NN] = EP;           // total is constant
}

__global__ void scan3_kernel() {           // per-node offsets; reset g_deg
    const int b = blockIdx.x;
    const int t = threadIdx.x;
    const int i = b * SB + t;
    int v = (i < NN) ? g_deg[i] : 0;
    __shared__ int sh[256];
    sh[t] = v;
    __syncthreads();
    for (int o = 1; o < 256; o <<= 1) {
        int u = (t >= o) ? sh[t - o] : 0;
        __syncthreads();
        sh[t] += u;
        __syncthreads();
    }
    const int excl = sh[t] - v + g_boff[b];
    if (i < NN) {
        g_offs[i] = excl;
        g_cursor[i] = excl;
        g_deg[i] = 0;                      // reset for next replay
    }
}

// ---------------- scatter edges into destination-sorted order ----------------
__global__ void scatter_kernel(const int* __restrict__ ei) {
    int e = blockIdx.x * blockDim.x + threadIdx.x;
    if (e < EP) {
        int row, col;
        if (e < EE) { row = ei[e]; col = ei[EE + e]; }
        else        { row = e - EE; col = row; }
        int pos = atomicAdd(&g_cursor[row], 1);
        g_scol[pos] = col;
    }
}

// -------- per-node attention aggregation (one warp per node, fp16 gathers) ---
__global__ __launch_bounds__(256) void aggregate_kernel(
    const float* __restrict__ bias, float* __restrict__ out)
{
    const int n = (blockIdx.x * blockDim.x + threadIdx.x) >> 5;
    const int lane = threadIdx.x & 31;
    if (n >= NN) return;

    uint2 qu = *reinterpret_cast<const uint2*>(&g_Qh[(size_t)n * FF + lane * 4]);
    const float2 q0 = __half22float2(*reinterpret_cast<__half2*>(&qu.x));
    const float2 q1 = __half22float2(*reinterpret_cast<__half2*>(&qu.y));

    float a0 = 0.f, a1 = 0.f, a2 = 0.f, a3 = 0.f;
    float denom = 0.f;

    const int s = g_offs[n];
    const int e = g_offs[n + 1];
    int p = s;

    for (; p + 2 <= e; p += 2) {
        const int c0 = g_scol[p];
        const int c1 = g_scol[p + 1];
        uint2 k0 = *reinterpret_cast<const uint2*>(&g_Kh[(size_t)c0 * FF + lane * 4]);
        uint2 k1 = *reinterpret_cast<const uint2*>(&g_Kh[(size_t)c1 * FF + lane * 4]);
        uint2 v0 = *reinterpret_cast<const uint2*>(&g_Vh[(size_t)c0 * FF + lane * 4]);
        uint2 v1 = *reinterpret_cast<const uint2*>(&g_Vh[(size_t)c1 * FF + lane * 4]);

        float2 ka = __half22float2(*reinterpret_cast<__half2*>(&k0.x));
        float2 kb = __half22float2(*reinterpret_cast<__half2*>(&k0.y));
        float d0 = q0.x * ka.x + q0.y * ka.y + q1.x * kb.x + q1.y * kb.y;
        ka = __half22float2(*reinterpret_cast<__half2*>(&k1.x));
        kb = __half22float2(*reinterpret_cast<__half2*>(&k1.y));
        float d1 = q0.x * ka.x + q0.y * ka.y + q1.x * kb.x + q1.y * kb.y;

        d0 += __shfl_xor_sync(0xffffffff, d0, 1);
        d1 += __shfl_xor_sync(0xffffffff, d1, 1);
        d0 += __shfl_xor_sync(0xffffffff, d0, 2);
        d1 += __shfl_xor_sync(0xffffffff, d1, 2);

        const float w0 = __expf(d0 * 0.25f);
        const float w1 = __expf(d1 * 0.25f);

        float2 va = __half22float2(*reinterpret_cast<__half2*>(&v0.x));
        float2 vb = __half22float2(*reinterpret_cast<__half2*>(&v0.y));
        a0 = fmaf(w0, va.x, a0); a1 = fmaf(w0, va.y, a1);
        a2 = fmaf(w0, vb.x, a2); a3 = fmaf(w0, vb.y, a3);
        va = __half22float2(*reinterpret_cast<__half2*>(&v1.x));
        vb = __half22float2(*reinterpret_cast<__half2*>(&v1.y));
        a0 = fmaf(w1, va.x, a0); a1 = fmaf(w1, va.y, a1);
        a2 = fmaf(w1, vb.x, a2); a3 = fmaf(w1, vb.y, a3);
        denom += w0 + w1;
    }
    for (; p < e; p++) {
        const int c0 = g_scol[p];
        uint2 k0 = *reinterpret_cast<const uint2*>(&g_Kh[(size_t)c0 * FF + lane * 4]);
        float2 ka = __half22float2(*reinterpret_cast<__half2*>(&k0.x));
        float2 kb = __half22float2(*reinterpret_cast<__half2*>(&k0.y));
        float d0 = q0.x * ka.x + q0.y * ka.y + q1.x * kb.x + q1.y * kb.y;
        d0 += __shfl_xor_sync(0xffffffff, d0, 1);
        d0 += __shfl_xor_sync(0xffffffff, d0, 2);
        const float w0 = __expf(d0 * 0.25f);
        uint2 v0 = *reinterpret_cast<const uint2*>(&g_Vh[(size_t)c0 * FF + lane * 4]);
        float2 va = __half22float2(*reinterpret_cast<__half2*>(&v0.x));
        float2 vb = __half22float2(*reinterpret_cast<__half2*>(&v0.y));
        a0 = fmaf(w0, va.x, a0); a1 = fmaf(w0, va.y, a1);
        a2 = fmaf(w0, vb.x, a2); a3 = fmaf(w0, vb.y, a3);
        denom += w0;
    }

    const float inv = 1.f / denom;   // >= 1 edge guaranteed (self loop)
    const float4 b = *reinterpret_cast<const float4*>(&bias[lane * 4]);
    float4 o;
    o.x = fmaf(a0, inv, b.x);
    o.y = fmaf(a1, inv, b.y);
    o.z = fmaf(a2, inv, b.z);
    o.w = fmaf(a3, inv, b.w);
    *reinterpret_cast<float4*>(&out[(size_t)n * FF + lane * 4]) = o;
}

// ---------------- launch ----------------
extern "C" void kernel_launch(void* const* d_in, const int* in_sizes, int n_in,
                              void* d_out, int out_size)
{
    const float* x    = (const float*)d_in[0];
    const int*   ei   = (const int*)d_in[1];     // JAX x64 disabled -> int32
    const int*   idix = (const int*)d_in[2];
    const float* Wq   = (const float*)d_in[3];
    const float* bq   = (const float*)d_in[4];
    const float* Wk   = (const float*)d_in[5];
    const float* bk   = (const float*)d_in[6];
    const float* Wv   = (const float*)d_in[7];
    const float* Wid  = (const float*)d_in[8];
    const float* bo   = (const float*)d_in[9];
    float* out = (float*)d_out;

    static bool attr_done = false;
    if (!attr_done) {
        cudaFuncSetAttribute(gemm3_kernel,
                             cudaFuncAttributeMaxDynamicSharedMemorySize, GEMM_SMEM);
        attr_done = true;
    }

    // counting sort of edges by destination (needs g_deg==0; scan3 resets it)
    hist_kernel<<<(EP + 255) / 256, 256>>>(ei);
    scan1_kernel<<<NSB, SB>>>();
    scan2_kernel<<<1, 256>>>();
    scan3_kernel<<<NSB, SB>>>();
    scatter_kernel<<<(EP + 255) / 256, 256>>>(ei);

    // Q/K/V GEMMs (tf32 tensor cores, 3-stage cp.async, fp16 outputs)
    dim3 ggrid((NN + 127) / 128, 3);
    gemm3_kernel<<<ggrid, 256, GEMM_SMEM>>>(x, Wq, bq, Wk, bk, Wv);

    // id scatter-add GEMM into V
    idgemm_kernel<<<(NID + IDB - 1) / IDB, 256>>>(x, idix, Wid);

    // fused attention softmax + aggregation, one warp per node
    aggregate_kernel<<<(NN * 32 + 255) / 256, 256>>>(bo, out);
}